// round 5
// baseline (speedup 1.0000x reference)
#include <cuda_runtime.h>
#include <cuda_bf16.h>
#include <cstdint>

#define HH 512
#define WW 512
#define DH 256
#define HWp (HH*WW)          // 262144
#define BB 2
#define MROWS (BB*HWp)       // 524288

// ---------------- scratch (device globals; no allocation allowed) ----------
__device__ float g_down_x[BB*3*DH*DH];                     // 1.5 MB
__device__ float g_out_full[BB*3*HH*WW];                   // 6 MB
__device__ float g_out256[BB*3*DH*DH];                     // 1.5 MB
__device__ float g_feat_tmp[BB*64*128*128];                // 8 MB
__device__ __align__(16) __nv_bfloat16 g_wHi[5][16384];    // [k][n] row-major, n padded to 128
__device__ __align__(16) __nv_bfloat16 g_wLo[5][16384];

// ---------------- mma/ldmatrix helpers (base ISA only) ----------------------
__device__ __forceinline__ uint32_t smem_u32(const void* p) {
    uint32_t a;
    asm("{ .reg .u64 t; cvta.to.shared.u64 t, %1; cvt.u32.u64 %0, t; }" : "=r"(a) : "l"(p));
    return a;
}
__device__ __forceinline__ void ldsm_x4(uint32_t addr, uint32_t r[4]) {
    asm volatile("ldmatrix.sync.aligned.m8n8.x4.shared.b16 {%0,%1,%2,%3}, [%4];"
        : "=r"(r[0]), "=r"(r[1]), "=r"(r[2]), "=r"(r[3]) : "r"(addr));
}
__device__ __forceinline__ void ldsm_x4t(uint32_t addr, uint32_t r[4]) {
    asm volatile("ldmatrix.sync.aligned.m8n8.x4.trans.shared.b16 {%0,%1,%2,%3}, [%4];"
        : "=r"(r[0]), "=r"(r[1]), "=r"(r[2]), "=r"(r[3]) : "r"(addr));
}
__device__ __forceinline__ void mma_bf16(float d[4], const uint32_t a[4], const uint32_t* b) {
    asm volatile("mma.sync.aligned.m16n8k16.row.col.f32.bf16.bf16.f32 "
        "{%0,%1,%2,%3}, {%4,%5,%6,%7}, {%8,%9}, {%0,%1,%2,%3};"
        : "+f"(d[0]), "+f"(d[1]), "+f"(d[2]), "+f"(d[3])
        : "r"(a[0]), "r"(a[1]), "r"(a[2]), "r"(a[3]), "r"(b[0]), "r"(b[1]));
}

// ---------------- bicubic tap helpers (match jax.image.resize, a=-0.5) -----
__device__ __forceinline__ void taps_down2(int o, int n, int idx[4], float w[4]) {
    const float kw0 = -0.0625f, kw1 = 0.5625f;
    float kw[4] = {kw0, kw1, kw1, kw0};
    float s = 0.f;
#pragma unroll
    for (int t = 0; t < 4; ++t) {
        int i = 2*o - 1 + t;
        bool ok = (i >= 0) && (i < n);
        idx[t] = ok ? i : 0;
        w[t]   = ok ? kw[t] : 0.f;
        s += w[t];
    }
    float inv = 1.f / s;
#pragma unroll
    for (int t = 0; t < 4; ++t) w[t] *= inv;
}
__device__ __forceinline__ void taps_up2(int o, int n, int idx[4], float w[4]) {
    int m = o >> 1;
    float kw[4];
    int base;
    if ((o & 1) == 0) {
        base = m - 2;
        kw[0] = -0.0234375f; kw[1] = 0.2265625f; kw[2] = 0.8671875f; kw[3] = -0.0703125f;
    } else {
        base = m - 1;
        kw[0] = -0.0703125f; kw[1] = 0.8671875f; kw[2] = 0.2265625f; kw[3] = -0.0234375f;
    }
    float s = 0.f;
#pragma unroll
    for (int t = 0; t < 4; ++t) {
        int i = base + t;
        bool ok = (i >= 0) && (i < n);
        idx[t] = ok ? i : 0;
        w[t]   = ok ? kw[t] : 0.f;
        s += w[t];
    }
    float inv = 1.f / s;
#pragma unroll
    for (int t = 0; t < 4; ++t) w[t] *= inv;
}

// ---------------- bicubic 2x down / up --------------------------------------
__global__ void k_down2(const float* __restrict__ in, float* __restrict__ out1,
                        float* __restrict__ out2, int Cn, int n_in)
{
    int n_out = n_in >> 1;
    long total = (long)Cn * n_out * n_out;
    long t = (long)blockIdx.x * blockDim.x + threadIdx.x;
    if (t >= total) return;
    int ox = (int)(t % n_out);
    int oy = (int)((t / n_out) % n_out);
    long c = t / ((long)n_out * n_out);
    int iy[4], ix[4]; float wy[4], wx[4];
    taps_down2(oy, n_in, iy, wy);
    taps_down2(ox, n_in, ix, wx);
    const float* ip = in + c * n_in * n_in;
    float s = 0.f;
#pragma unroll
    for (int a = 0; a < 4; ++a) {
        float r = 0.f;
#pragma unroll
        for (int b2 = 0; b2 < 4; ++b2) r += wx[b2] * ip[iy[a]*n_in + ix[b2]];
        s += wy[a] * r;
    }
    out1[t] = s;
    if (out2) out2[t] = s;
}
__global__ void k_up2(const float* __restrict__ in, float* __restrict__ outp,
                      int Cn, int n_in)
{
    int n_out = n_in << 1;
    long total = (long)Cn * n_out * n_out;
    long t = (long)blockIdx.x * blockDim.x + threadIdx.x;
    if (t >= total) return;
    int ox = (int)(t % n_out);
    int oy = (int)((t / n_out) % n_out);
    long c = t / ((long)n_out * n_out);
    int iy[4], ix[4]; float wy[4], wx[4];
    taps_up2(oy, n_in, iy, wy);
    taps_up2(ox, n_in, ix, wx);
    const float* ip = in + c * n_in * n_in;
    float s = 0.f;
#pragma unroll
    for (int a = 0; a < 4; ++a) {
        float r = 0.f;
#pragma unroll
        for (int b2 = 0; b2 < 4; ++b2) r += wx[b2] * ip[iy[a]*n_in + ix[b2]];
        s += wy[a] * r;
    }
    outp[t] = s;
}

// ---------------- weight prep: f32 -> (hi,lo) bf16, [k][n] n-padded --------
__global__ void k_prep_w(const float* __restrict__ W1, const float* __restrict__ W2,
                         const float* __restrict__ W3, const float* __restrict__ W4,
                         const float* __restrict__ Wout)
{
    int t = blockIdx.x * 256 + threadIdx.x;     // 5*16384 = 81920
    if (t >= 81920) return;
    int L = t >> 14, r = t & 16383;
    int k = r >> 7, n = r & 127;
    const float* W = (L == 0) ? W1 : (L == 1) ? W2 : (L == 2) ? W3 : (L == 3) ? W4 : Wout;
    float v = (L < 4) ? W[k * 128 + n] : ((n < 81) ? W[k * 81 + n] : 0.f);
    __nv_bfloat16 h = __float2bfloat16(v);
    g_wHi[L][r] = h;
    g_wLo[L][r] = __float2bfloat16(v - __bfloat162float(h));
}

// ---------------- fused MLP + dynamic-filter apply --------------------------
// SMEM: padded rows of 272B (136 bf16) for conflict-free ldmatrix.
#define ROWB 272
#define S_AHI 0
#define S_ALO 34816
#define S_BHI 69632            // also reused: lwS (128 x 84 f32 = 43008B)
#define S_BLO 104448
#define S_INP 139264           // 128*8 f32; also reused: x patch (3*3*132 f32 = 4752B)
#define S_WIN 144128           // 7*128 f32 = 3584
#define S_TOT 147712
#define LWST 84                // lwS row stride (floats)

__device__ __forceinline__ void st_hilo2(char* smem, int row, int col,
                                         float v0, float v1)
{
    __nv_bfloat16 h0 = __float2bfloat16(v0);
    __nv_bfloat16 h1 = __float2bfloat16(v1);
    __nv_bfloat16 l0 = __float2bfloat16(v0 - __bfloat162float(h0));
    __nv_bfloat16 l1 = __float2bfloat16(v1 - __bfloat162float(h1));
    __nv_bfloat162 hp; hp.x = h0; hp.y = h1;
    __nv_bfloat162 lp; lp.x = l0; lp.y = l1;
    int off = row * ROWB + col * 2;
    *(uint32_t*)(smem + S_AHI + off) = *(uint32_t*)&hp;
    *(uint32_t*)(smem + S_ALO + off) = *(uint32_t*)&lp;
}

__global__ __launch_bounds__(512, 1) void fused_mlp_mma(
    const float* __restrict__ x, const float* __restrict__ Win,
    float* __restrict__ outp)
{
    extern __shared__ __align__(16) char smem[];
    const uint32_t sb = smem_u32(smem);
    const int tid = threadIdx.x;
    const int wid = tid >> 5, lane = tid & 31;
    const long row0 = (long)blockIdx.x * 128;
    const int bimg = (int)(row0 >> 18);
    const int n0 = (int)(row0 & (HWp - 1));
    const int irow = n0 >> 9, j0 = n0 & 511;

    // ---- stage W_in, per-pixel inputs ----
    for (int i = tid; i < 896; i += 512) *(float*)(smem + S_WIN + i*4) = Win[i];
    if (tid < 128) {
        int i = irow, j = j0 + tid;
        int iy[4], ix[4]; float wy[4], wx[4];
        taps_up2(i, DH, iy, wy);
        taps_up2(j, DH, ix, wx);
        float* ip = (float*)(smem + S_INP) + tid * 8;
        ip[0] = (i & 1) ? 0.5f : -0.5f;
        ip[1] = (j & 1) ? 0.5f : -0.5f;
        ip[2] = 1.f; ip[3] = 1.f;
#pragma unroll
        for (int c = 0; c < 3; ++c) {
            const float* dp = g_down_x + (long)(bimg*3 + c) * DH * DH;
            float s = 0.f;
#pragma unroll
            for (int a = 0; a < 4; ++a) {
                float rr = 0.f;
#pragma unroll
                for (int b2 = 0; b2 < 4; ++b2) rr += wx[b2] * dp[iy[a]*DH + ix[b2]];
                s += wy[a] * rr;
            }
            ip[4 + c] = x[((long)(bimg*3 + c) * HH + i) * WW + j] - s;
        }
        ip[7] = 0.f;
    }
    __syncthreads();

    // ---- layer 0 (7 -> 128) SIMT, write A hi/lo ----
    {
        int row = tid >> 2;
        int cbase = (tid & 3) * 32;
        const float* ip = (const float*)(smem + S_INP) + row * 8;
        float a0 = ip[0], a1 = ip[1], a2 = ip[2], a3 = ip[3];
        float a4 = ip[4], a5 = ip[5], a6 = ip[6];
        const float* Wn = (const float*)(smem + S_WIN);
#pragma unroll 4
        for (int c = 0; c < 32; c += 2) {
            int o = cbase + c;
            float v0 = a0*Wn[o] + a1*Wn[128+o] + a2*Wn[256+o] + a3*Wn[384+o]
                     + a4*Wn[512+o] + a5*Wn[640+o] + a6*Wn[768+o];
            float v1 = a0*Wn[o+1] + a1*Wn[128+o+1] + a2*Wn[256+o+1] + a3*Wn[384+o+1]
                     + a4*Wn[512+o+1] + a5*Wn[640+o+1] + a6*Wn[768+o+1];
            v0 = v0 > 0.f ? v0 : 0.01f * v0;
            v1 = v1 > 0.f ? v1 : 0.01f * v1;
            st_hilo2(smem, row, o, v0, v1);
        }
    }

    // ---- warp tiling: 4 (m) x 4 (n); warp tile = 32 rows x 32 cols ----
    const int wm = wid & 3, wn = wid >> 2;
    const uint32_t aAddr = sb + S_AHI + (uint32_t)((wm*32 + (lane & 15)) * ROWB + (lane >> 4) * 16);
    const uint32_t bAddr = sb + S_BHI + (uint32_t)((lane & 15) * ROWB + (wn*32)*2 + (lane >> 4) * 16);

#pragma unroll 1
    for (int L = 0; L < 5; ++L) {
        // stage layer weights hi/lo into smem padded rows
        {
            const uint4* srcH = (const uint4*)g_wHi[L];
            const uint4* srcL = (const uint4*)g_wLo[L];
#pragma unroll
            for (int it = 0; it < 4; ++it) {
                int idx = it * 512 + tid;         // 2048 uint4 = 16384 bf16
                int row = idx >> 4, col = (idx & 15) * 8;
                *(uint4*)(smem + S_BHI + row * ROWB + col * 2) = srcH[idx];
                *(uint4*)(smem + S_BLO + row * ROWB + col * 2) = srcL[idx];
            }
        }
        __syncthreads();

        float acc[2][4][4];
#pragma unroll
        for (int mt = 0; mt < 2; ++mt)
#pragma unroll
            for (int nt = 0; nt < 4; ++nt)
#pragma unroll
                for (int q = 0; q < 4; ++q) acc[mt][nt][q] = 0.f;

#pragma unroll 1
        for (int k = 0; k < 8; ++k) {
            uint32_t ah[2][4], al[2][4];
#pragma unroll
            for (int mt = 0; mt < 2; ++mt) {
                uint32_t a = aAddr + (uint32_t)(mt * 16 * ROWB + k * 32);
                ldsm_x4(a, ah[mt]);
                ldsm_x4(a + (S_ALO - S_AHI), al[mt]);
            }
#pragma unroll
            for (int np = 0; np < 2; ++np) {
                uint32_t bh[4], bl[4];
                uint32_t b = bAddr + (uint32_t)(k * 16 * ROWB + np * 32);
                ldsm_x4t(b, bh);
                ldsm_x4t(b + (S_BLO - S_BHI), bl);
#pragma unroll
                for (int mt = 0; mt < 2; ++mt) {
                    mma_bf16(acc[mt][np*2],   ah[mt], bh);
                    mma_bf16(acc[mt][np*2+1], ah[mt], bh + 2);
                    mma_bf16(acc[mt][np*2],   ah[mt], bl);
                    mma_bf16(acc[mt][np*2+1], ah[mt], bl + 2);
                    mma_bf16(acc[mt][np*2],   al[mt], bh);
                    mma_bf16(acc[mt][np*2+1], al[mt], bh + 2);
                }
            }
        }
        __syncthreads();   // all warps done reading A/B before overwriting

        if (L < 4) {
#pragma unroll
            for (int mt = 0; mt < 2; ++mt) {
                int r0 = wm*32 + mt*16 + (lane >> 2);
#pragma unroll
                for (int nt = 0; nt < 4; ++nt) {
                    int c = wn*32 + nt*8 + (lane & 3)*2;
                    float v0 = acc[mt][nt][0], v1 = acc[mt][nt][1];
                    float w0 = acc[mt][nt][2], w1 = acc[mt][nt][3];
                    v0 = v0 > 0.f ? v0 : 0.01f * v0;
                    v1 = v1 > 0.f ? v1 : 0.01f * v1;
                    w0 = w0 > 0.f ? w0 : 0.01f * w0;
                    w1 = w1 > 0.f ? w1 : 0.01f * w1;
                    st_hilo2(smem, r0,     c, v0, v1);
                    st_hilo2(smem, r0 + 8, c, w0, w1);
                }
            }
            __syncthreads();
        } else {
            // output layer: dump cols < 81 into lwS (reuses B buffer region)
            float* lwS = (float*)(smem + S_BHI);
#pragma unroll
            for (int mt = 0; mt < 2; ++mt) {
                int r0 = wm*32 + mt*16 + (lane >> 2);
#pragma unroll
                for (int nt = 0; nt < 4; ++nt) {
                    int c = wn*32 + nt*8 + (lane & 3)*2;
                    if (c < 81) {
                        lwS[r0 * LWST + c]       = acc[mt][nt][0];
                        lwS[(r0+8) * LWST + c]   = acc[mt][nt][2];
                    }
                    if (c + 1 < 81) {
                        lwS[r0 * LWST + c + 1]     = acc[mt][nt][1];
                        lwS[(r0+8) * LWST + c + 1] = acc[mt][nt][3];
                    }
                }
            }
        }
    }

    // ---- stage 3ch x 3row x 130col x patch (zero padded) ----
    float* xp = (float*)(smem + S_INP);        // [3][3][132]
    for (int idx = tid; idx < 3*3*130; idx += 512) {
        int c = idx / 390, rem = idx % 390, ki = rem / 130, jj = rem % 130;
        int yy = irow + ki - 1;
        int xx = j0 + jj - 1;
        float v = 0.f;
        if (yy >= 0 && yy < HH && xx >= 0 && xx < WW)
            v = x[((long)(bimg*3 + c) * HH + yy) * WW + xx];
        xp[(c*3 + ki) * 132 + jj] = v;
    }
    __syncthreads();

    // ---- apply: 384 threads = 128 pixels x 3 out channels ----
    if (tid < 384) {
        int p = tid & 127, oc = tid >> 7;
        const float* lwr = (const float*)(smem + S_BHI) + p * LWST;
        float o = 0.f;
#pragma unroll
        for (int c = 0; c < 3; ++c)
#pragma unroll
            for (int ki = 0; ki < 3; ++ki) {
                const float* xr = xp + (c*3 + ki) * 132 + p;
#pragma unroll
                for (int kj = 0; kj < 3; ++kj)
                    o += xr[kj] * lwr[(c*9 + ki*3 + kj) * 3 + oc];
            }
        outp[(long)(bimg*3 + oc) * HWp + n0 + p] = o;
    }
}

// ---------------- 3x3 stride-2 pad-1 conv, 3 -> 64 channels -----------------
__global__ __launch_bounds__(256) void k_conv3x3s2(const float* __restrict__ in,
    const float* __restrict__ wt, const float* __restrict__ bias,
    float* __restrict__ outp, int S)
{
    __shared__ float w_s[1728];
    __shared__ float in_s[3][33][33];
    int tid = threadIdx.x;
    for (int i = tid; i < 1728; i += 256) w_s[i] = wt[i];
    int OS = S >> 1;
    int ox0 = blockIdx.x * 16, oy0 = blockIdx.y * 16, b = blockIdx.z;
    for (int idx = tid; idx < 3*33*33; idx += 256) {
        int c = idx / 1089, rem = idx % 1089, r = rem / 33, col = rem % 33;
        int iy = oy0*2 - 1 + r, ix = ox0*2 - 1 + col;
        float v = 0.f;
        if (iy >= 0 && iy < S && ix >= 0 && ix < S)
            v = in[((long)(b*3 + c) * S + iy) * S + ix];
        in_s[c][r][col] = v;
    }
    __syncthreads();
    int ox = tid & 15, oy = tid >> 4;
    float pix[27];
#pragma unroll
    for (int c = 0; c < 3; ++c)
#pragma unroll
        for (int ki = 0; ki < 3; ++ki)
#pragma unroll
            for (int kj = 0; kj < 3; ++kj)
                pix[c*9 + ki*3 + kj] = in_s[c][2*oy + ki][2*ox + kj];
#pragma unroll 4
    for (int oc = 0; oc < 64; ++oc) {
        float acc = bias[oc];
#pragma unroll
        for (int q = 0; q < 27; ++q) acc += pix[q] * w_s[oc*27 + q];
        outp[(((long)b*64 + oc) * OS + oy0 + oy) * OS + ox0 + ox] = acc;
    }
}

// ---------------- 1x1 mod conv ----------------------------------------------
__global__ void k_mod(const float* __restrict__ dx, const float* __restrict__ o256,
                      const float* __restrict__ mw, const float* __restrict__ mb,
                      float* __restrict__ outp)
{
    int t = blockIdx.x * 256 + threadIdx.x;
    if (t >= BB * DH * DH) return;
    int b = t >> 16, p = t & 65535;
    float in6[6];
#pragma unroll
    for (int c = 0; c < 3; ++c) in6[c]     = dx[(b*3 + c)*65536 + p];
#pragma unroll
    for (int c = 0; c < 3; ++c) in6[3 + c] = o256[(b*3 + c)*65536 + p];
#pragma unroll
    for (int oc = 0; oc < 3; ++oc) {
        float a = mb[oc];
#pragma unroll
        for (int ic = 0; ic < 6; ++ic) a += in6[ic] * mw[oc*6 + ic];
        outp[(b*3 + oc)*65536 + p] = a;
    }
}

// ---------------- launch -----------------------------------------------------
extern "C" void kernel_launch(void* const* d_in, const int* in_sizes, int n_in,
                              void* d_out, int out_size)
{
    const float* x      = (const float*)d_in[0];
    const float* W_in   = (const float*)d_in[1];
    const float* W_h1   = (const float*)d_in[2];
    const float* W_h2   = (const float*)d_in[3];
    const float* W_h3   = (const float*)d_in[4];
    const float* W_h4   = (const float*)d_in[5];
    const float* W_out  = (const float*)d_in[6];
    const float* feat_w = (const float*)d_in[7];
    const float* feat_b = (const float*)d_in[8];
    const float* mod_w  = (const float*)d_in[9];
    const float* mod_b  = (const float*)d_in[10];

    float* outF = (float*)d_out;
    float* dout_mod = outF;                       // 2*3*256*256   = 393216
    float* dout_hr  = outF + 393216;              // 2*64*256*256  = 8388608
    float* dout_new = outF + 8781824;             // 8388608
    float* dout_ori = outF + 17170432;            // 8388608
    float* dout_out = outF + 25559040;            // 393216

    float *downx, *outfull, *out256, *ftmp;
    cudaGetSymbolAddress((void**)&downx,   g_down_x);
    cudaGetSymbolAddress((void**)&outfull, g_out_full);
    cudaGetSymbolAddress((void**)&out256,  g_out256);
    cudaGetSymbolAddress((void**)&ftmp,    g_feat_tmp);

    static int smem_set = 0;
    if (!smem_set) {
        cudaFuncSetAttribute(fused_mlp_mma, cudaFuncAttributeMaxDynamicSharedMemorySize,
                             S_TOT);
        smem_set = 1;
    }

    // 1. down_x = bicubic_down2(x)
    k_down2<<<(BB*3*DH*DH + 255)/256, 256>>>(x, downx, nullptr, BB*3, HH);
    // 2. weight split/prep into bf16 hi/lo [k][n]
    k_prep_w<<<320, 256>>>(W_h1, W_h2, W_h3, W_h4, W_out);
    // 3. fused tensor-core MLP + dynamic-filter apply -> out_full
    fused_mlp_mma<<<MROWS/128, 512, S_TOT>>>(x, W_in, outfull);
    // 4. out = down2(out_full); keep copy for mod conv
    k_down2<<<(BB*3*DH*DH + 255)/256, 256>>>(outfull, out256, dout_out, BB*3, HH);
    // 5. down_x_mod = 1x1 conv(concat(down_x, out))
    k_mod<<<(BB*DH*DH + 255)/256, 256>>>(downx, out256, mod_w, mod_b, dout_mod);
    // 6. hr_feature = conv3x3s2(x)
    {
        dim3 g(16, 16, BB);
        k_conv3x3s2<<<g, 256>>>(x, feat_w, feat_b, dout_hr, 512);
    }
    // 7. ori_lr_feature = up2(conv3x3s2(down_x))
    {
        dim3 g(8, 8, BB);
        k_conv3x3s2<<<g, 256>>>(downx, feat_w, feat_b, ftmp, 256);
    }
    k_up2<<<(BB*64*256*256 + 255)/256, 256>>>(ftmp, dout_ori, BB*64, 128);
    // 8. new_lr_feature = up2(conv3x3s2(down_x_mod))
    {
        dim3 g(8, 8, BB);
        k_conv3x3s2<<<g, 256>>>(dout_mod, feat_w, feat_b, ftmp, 256);
    }
    k_up2<<<(BB*64*256*256 + 255)/256, 256>>>(ftmp, dout_new, BB*64, 128);
}

// round 6
// speedup vs baseline: 1.1255x; 1.1255x over previous
#include <cuda_runtime.h>
#include <cuda_bf16.h>
#include <cstdint>

#define HH 512
#define WW 512
#define DH 256
#define HWp (HH*WW)          // 262144
#define BB 2
#define MROWS (BB*HWp)       // 524288

// ---------------- scratch (device globals; no allocation allowed) ----------
__device__ float g_down_x[BB*3*DH*DH];                     // 1.5 MB
__device__ float g_out_full[BB*3*HH*WW];                   // 6 MB
__device__ float g_out256[BB*3*DH*DH];                     // 1.5 MB
__device__ float g_feat_tmp[BB*64*128*128];                // 8 MB
__device__ __align__(16) __nv_bfloat16 g_wHi[5][16384];    // [k][n] row-major, n padded to 128
__device__ __align__(16) __nv_bfloat16 g_wLo[5][16384];

// ---------------- mma/ldmatrix helpers (base ISA only) ----------------------
__device__ __forceinline__ uint32_t smem_u32(const void* p) {
    uint32_t a;
    asm("{ .reg .u64 t; cvta.to.shared.u64 t, %1; cvt.u32.u64 %0, t; }" : "=r"(a) : "l"(p));
    return a;
}
__device__ __forceinline__ void ldsm_x4(uint32_t addr, uint32_t r[4]) {
    asm volatile("ldmatrix.sync.aligned.m8n8.x4.shared.b16 {%0,%1,%2,%3}, [%4];"
        : "=r"(r[0]), "=r"(r[1]), "=r"(r[2]), "=r"(r[3]) : "r"(addr));
}
__device__ __forceinline__ void ldsm_x4t(uint32_t addr, uint32_t r[4]) {
    asm volatile("ldmatrix.sync.aligned.m8n8.x4.trans.shared.b16 {%0,%1,%2,%3}, [%4];"
        : "=r"(r[0]), "=r"(r[1]), "=r"(r[2]), "=r"(r[3]) : "r"(addr));
}
__device__ __forceinline__ void mma_bf16(float d[4], const uint32_t a[4], const uint32_t* b) {
    asm volatile("mma.sync.aligned.m16n8k16.row.col.f32.bf16.bf16.f32 "
        "{%0,%1,%2,%3}, {%4,%5,%6,%7}, {%8,%9}, {%0,%1,%2,%3};"
        : "+f"(d[0]), "+f"(d[1]), "+f"(d[2]), "+f"(d[3])
        : "r"(a[0]), "r"(a[1]), "r"(a[2]), "r"(a[3]), "r"(b[0]), "r"(b[1]));
}

// ---------------- bicubic tap helpers (match jax.image.resize, a=-0.5) -----
__device__ __forceinline__ void taps_down2(int o, int n, int idx[4], float w[4]) {
    const float kw0 = -0.0625f, kw1 = 0.5625f;
    float kw[4] = {kw0, kw1, kw1, kw0};
    float s = 0.f;
#pragma unroll
    for (int t = 0; t < 4; ++t) {
        int i = 2*o - 1 + t;
        bool ok = (i >= 0) && (i < n);
        idx[t] = ok ? i : 0;
        w[t]   = ok ? kw[t] : 0.f;
        s += w[t];
    }
    float inv = 1.f / s;
#pragma unroll
    for (int t = 0; t < 4; ++t) w[t] *= inv;
}
__device__ __forceinline__ void taps_up2(int o, int n, int idx[4], float w[4]) {
    int m = o >> 1;
    float kw[4];
    int base;
    if ((o & 1) == 0) {
        base = m - 2;
        kw[0] = -0.0234375f; kw[1] = 0.2265625f; kw[2] = 0.8671875f; kw[3] = -0.0703125f;
    } else {
        base = m - 1;
        kw[0] = -0.0703125f; kw[1] = 0.8671875f; kw[2] = 0.2265625f; kw[3] = -0.0234375f;
    }
    float s = 0.f;
#pragma unroll
    for (int t = 0; t < 4; ++t) {
        int i = base + t;
        bool ok = (i >= 0) && (i < n);
        idx[t] = ok ? i : 0;
        w[t]   = ok ? kw[t] : 0.f;
        s += w[t];
    }
    float inv = 1.f / s;
#pragma unroll
    for (int t = 0; t < 4; ++t) w[t] *= inv;
}

// ---------------- bicubic 2x down / up --------------------------------------
__global__ void k_down2(const float* __restrict__ in, float* __restrict__ out1,
                        float* __restrict__ out2, int Cn, int n_in)
{
    int n_out = n_in >> 1;
    long total = (long)Cn * n_out * n_out;
    long t = (long)blockIdx.x * blockDim.x + threadIdx.x;
    if (t >= total) return;
    int ox = (int)(t % n_out);
    int oy = (int)((t / n_out) % n_out);
    long c = t / ((long)n_out * n_out);
    int iy[4], ix[4]; float wy[4], wx[4];
    taps_down2(oy, n_in, iy, wy);
    taps_down2(ox, n_in, ix, wx);
    const float* ip = in + c * n_in * n_in;
    float s = 0.f;
#pragma unroll
    for (int a = 0; a < 4; ++a) {
        float r = 0.f;
#pragma unroll
        for (int b2 = 0; b2 < 4; ++b2) r += wx[b2] * ip[iy[a]*n_in + ix[b2]];
        s += wy[a] * r;
    }
    out1[t] = s;
    if (out2) out2[t] = s;
}
__global__ void k_up2(const float* __restrict__ in, float* __restrict__ outp,
                      int Cn, int n_in)
{
    int n_out = n_in << 1;
    long total = (long)Cn * n_out * n_out;
    long t = (long)blockIdx.x * blockDim.x + threadIdx.x;
    if (t >= total) return;
    int ox = (int)(t % n_out);
    int oy = (int)((t / n_out) % n_out);
    long c = t / ((long)n_out * n_out);
    int iy[4], ix[4]; float wy[4], wx[4];
    taps_up2(oy, n_in, iy, wy);
    taps_up2(ox, n_in, ix, wx);
    const float* ip = in + c * n_in * n_in;
    float s = 0.f;
#pragma unroll
    for (int a = 0; a < 4; ++a) {
        float r = 0.f;
#pragma unroll
        for (int b2 = 0; b2 < 4; ++b2) r += wx[b2] * ip[iy[a]*n_in + ix[b2]];
        s += wy[a] * r;
    }
    outp[t] = s;
}

// ---------------- weight prep: f32 -> (hi,lo) bf16, [k][n] n-padded --------
__global__ void k_prep_w(const float* __restrict__ W1, const float* __restrict__ W2,
                         const float* __restrict__ W3, const float* __restrict__ W4,
                         const float* __restrict__ Wout)
{
    int t = blockIdx.x * 256 + threadIdx.x;     // 5*16384 = 81920
    if (t >= 81920) return;
    int L = t >> 14, r = t & 16383;
    int k = r >> 7, n = r & 127;
    const float* W = (L == 0) ? W1 : (L == 1) ? W2 : (L == 2) ? W3 : (L == 3) ? W4 : Wout;
    float v = (L < 4) ? W[k * 128 + n] : ((n < 81) ? W[k * 81 + n] : 0.f);
    __nv_bfloat16 h = __float2bfloat16(v);
    g_wHi[L][r] = h;
    g_wLo[L][r] = __float2bfloat16(v - __bfloat162float(h));
}

// ---------------- fused MLP + dynamic-filter apply --------------------------
// SMEM: padded rows of 272B (136 bf16) for conflict-free ldmatrix.
#define ROWB 272
#define S_AHI 0
#define S_ALO 34816
#define S_BHI 69632            // also reused: lwS (128 x 84 f32 = 43008B)
#define S_BLO 104448
#define S_INP 139264           // 128*8 f32; also reused: x patch (3*3*132 f32)
#define S_WIN 144128           // 7*128 f32 = 3584
#define S_TOT 147712
#define LWST 84                // lwS row stride (floats)

__device__ __forceinline__ void st_hilo2(char* smem, int row, int col,
                                         float v0, float v1)
{
    __nv_bfloat16 h0 = __float2bfloat16(v0);
    __nv_bfloat16 h1 = __float2bfloat16(v1);
    __nv_bfloat16 l0 = __float2bfloat16(v0 - __bfloat162float(h0));
    __nv_bfloat16 l1 = __float2bfloat16(v1 - __bfloat162float(h1));
    __nv_bfloat162 hp; hp.x = h0; hp.y = h1;
    __nv_bfloat162 lp; lp.x = l0; lp.y = l1;
    int off = row * ROWB + col * 2;
    *(uint32_t*)(smem + S_AHI + off) = *(uint32_t*)&hp;
    *(uint32_t*)(smem + S_ALO + off) = *(uint32_t*)&lp;
}

__global__ __launch_bounds__(256, 1) void fused_mlp_mma(
    const float* __restrict__ x, const float* __restrict__ Win,
    float* __restrict__ outp)
{
    extern __shared__ __align__(16) char smem[];
    const uint32_t sb = smem_u32(smem);
    const int tid = threadIdx.x;
    const int wid = tid >> 5, lane = tid & 31;
    const long row0 = (long)blockIdx.x * 128;
    const int bimg = (int)(row0 >> 18);
    const int n0 = (int)(row0 & (HWp - 1));
    const int irow = n0 >> 9, j0 = n0 & 511;

    // ---- stage W_in, per-pixel inputs ----
    for (int i = tid; i < 896; i += 256) *(float*)(smem + S_WIN + i*4) = Win[i];
    if (tid < 128) {
        int i = irow, j = j0 + tid;
        int iy[4], ix[4]; float wy[4], wx[4];
        taps_up2(i, DH, iy, wy);
        taps_up2(j, DH, ix, wx);
        float* ip = (float*)(smem + S_INP) + tid * 8;
        ip[0] = (i & 1) ? 0.5f : -0.5f;
        ip[1] = (j & 1) ? 0.5f : -0.5f;
        ip[2] = 1.f; ip[3] = 1.f;
#pragma unroll
        for (int c = 0; c < 3; ++c) {
            const float* dp = g_down_x + (long)(bimg*3 + c) * DH * DH;
            float s = 0.f;
#pragma unroll
            for (int a = 0; a < 4; ++a) {
                float rr = 0.f;
#pragma unroll
                for (int b2 = 0; b2 < 4; ++b2) rr += wx[b2] * dp[iy[a]*DH + ix[b2]];
                s += wy[a] * rr;
            }
            ip[4 + c] = x[((long)(bimg*3 + c) * HH + i) * WW + j] - s;
        }
        ip[7] = 0.f;
    }
    __syncthreads();

    // ---- layer 0 (7 -> 128) SIMT, write A hi/lo ----
    {
        int row = tid >> 1;
        int cbase = (tid & 1) * 64;
        const float* ip = (const float*)(smem + S_INP) + row * 8;
        float a0 = ip[0], a1 = ip[1], a2 = ip[2], a3 = ip[3];
        float a4 = ip[4], a5 = ip[5], a6 = ip[6];
        const float* Wn = (const float*)(smem + S_WIN);
#pragma unroll 8
        for (int c = 0; c < 64; c += 2) {
            int o = cbase + c;
            float v0 = a0*Wn[o] + a1*Wn[128+o] + a2*Wn[256+o] + a3*Wn[384+o]
                     + a4*Wn[512+o] + a5*Wn[640+o] + a6*Wn[768+o];
            float v1 = a0*Wn[o+1] + a1*Wn[128+o+1] + a2*Wn[256+o+1] + a3*Wn[384+o+1]
                     + a4*Wn[512+o+1] + a5*Wn[640+o+1] + a6*Wn[768+o+1];
            v0 = v0 > 0.f ? v0 : 0.01f * v0;
            v1 = v1 > 0.f ? v1 : 0.01f * v1;
            st_hilo2(smem, row, o, v0, v1);
        }
    }

    // ---- warp tiling: 4 (m) x 2 (n); warp tile = 32 rows x 64 cols ----
    const int wm = wid & 3, wn = wid >> 2;
    const uint32_t aAddr = sb + S_AHI + (uint32_t)((wm*32 + (lane & 15)) * ROWB + (lane >> 4) * 16);
    const uint32_t bAddr = sb + S_BHI + (uint32_t)((lane & 15) * ROWB + (wn*64)*2 + (lane >> 4) * 16);

#pragma unroll 1
    for (int L = 0; L < 5; ++L) {
        // stage layer weights hi/lo into smem padded rows
        {
            const uint4* srcH = (const uint4*)g_wHi[L];
            const uint4* srcL = (const uint4*)g_wLo[L];
#pragma unroll
            for (int it = 0; it < 8; ++it) {
                int idx = it * 256 + tid;         // 2048 uint4 = 16384 bf16
                int row = idx >> 4, col = (idx & 15) * 8;
                *(uint4*)(smem + S_BHI + row * ROWB + col * 2) = srcH[idx];
                *(uint4*)(smem + S_BLO + row * ROWB + col * 2) = srcL[idx];
            }
        }
        __syncthreads();

        float acc[2][8][4];
#pragma unroll
        for (int mt = 0; mt < 2; ++mt)
#pragma unroll
            for (int nt = 0; nt < 8; ++nt)
#pragma unroll
                for (int q = 0; q < 4; ++q) acc[mt][nt][q] = 0.f;

#pragma unroll 1
        for (int k = 0; k < 8; ++k) {
            uint32_t ah[2][4], al[2][4];
#pragma unroll
            for (int mt = 0; mt < 2; ++mt) {
                uint32_t a = aAddr + (uint32_t)(mt * 16 * ROWB + k * 32);
                ldsm_x4(a, ah[mt]);
                ldsm_x4(a + (S_ALO - S_AHI), al[mt]);
            }
#pragma unroll
            for (int np = 0; np < 4; ++np) {
                uint32_t bh[4], bl[4];
                uint32_t b = bAddr + (uint32_t)(k * 16 * ROWB + np * 32);
                ldsm_x4t(b, bh);
                ldsm_x4t(b + (S_BLO - S_BHI), bl);
                // 3 passes; consecutive MMAs hit distinct accumulators
                // (same-acc distance = 4 >= HMMA latency with 8 warps)
                mma_bf16(acc[0][np*2],   ah[0], bh);
                mma_bf16(acc[0][np*2+1], ah[0], bh + 2);
                mma_bf16(acc[1][np*2],   ah[1], bh);
                mma_bf16(acc[1][np*2+1], ah[1], bh + 2);
                mma_bf16(acc[0][np*2],   ah[0], bl);
                mma_bf16(acc[0][np*2+1], ah[0], bl + 2);
                mma_bf16(acc[1][np*2],   ah[1], bl);
                mma_bf16(acc[1][np*2+1], ah[1], bl + 2);
                mma_bf16(acc[0][np*2],   al[0], bh);
                mma_bf16(acc[0][np*2+1], al[0], bh + 2);
                mma_bf16(acc[1][np*2],   al[1], bh);
                mma_bf16(acc[1][np*2+1], al[1], bh + 2);
            }
        }
        __syncthreads();   // all warps done reading A/B before overwriting

        if (L < 4) {
#pragma unroll
            for (int mt = 0; mt < 2; ++mt) {
                int r0 = wm*32 + mt*16 + (lane >> 2);
#pragma unroll
                for (int nt = 0; nt < 8; ++nt) {
                    int c = wn*64 + nt*8 + (lane & 3)*2;
                    float v0 = acc[mt][nt][0], v1 = acc[mt][nt][1];
                    float w0 = acc[mt][nt][2], w1 = acc[mt][nt][3];
                    v0 = v0 > 0.f ? v0 : 0.01f * v0;
                    v1 = v1 > 0.f ? v1 : 0.01f * v1;
                    w0 = w0 > 0.f ? w0 : 0.01f * w0;
                    w1 = w1 > 0.f ? w1 : 0.01f * w1;
                    st_hilo2(smem, r0,     c, v0, v1);
                    st_hilo2(smem, r0 + 8, c, w0, w1);
                }
            }
            __syncthreads();
        } else {
            // output layer: dump cols < 81 into lwS (reuses B buffer region)
            float* lwS = (float*)(smem + S_BHI);
#pragma unroll
            for (int mt = 0; mt < 2; ++mt) {
                int r0 = wm*32 + mt*16 + (lane >> 2);
#pragma unroll
                for (int nt = 0; nt < 8; ++nt) {
                    int c = wn*64 + nt*8 + (lane & 3)*2;
                    if (c < 81) {
                        lwS[r0 * LWST + c]       = acc[mt][nt][0];
                        lwS[(r0+8) * LWST + c]   = acc[mt][nt][2];
                    }
                    if (c + 1 < 81) {
                        lwS[r0 * LWST + c + 1]     = acc[mt][nt][1];
                        lwS[(r0+8) * LWST + c + 1] = acc[mt][nt][3];
                    }
                }
            }
        }
    }

    // ---- stage 3ch x 3row x 130col x patch (zero padded) ----
    float* xp = (float*)(smem + S_INP);        // [3][3][132]
    for (int idx = tid; idx < 3*3*130; idx += 256) {
        int c = idx / 390, rem = idx % 390, ki = rem / 130, jj = rem % 130;
        int yy = irow + ki - 1;
        int xx = j0 + jj - 1;
        float v = 0.f;
        if (yy >= 0 && yy < HH && xx >= 0 && xx < WW)
            v = x[((long)(bimg*3 + c) * HH + yy) * WW + xx];
        xp[(c*3 + ki) * 132 + jj] = v;
    }
    __syncthreads();

    // ---- apply: 128 pixels x 3 out channels ----
    for (int idx = tid; idx < 384; idx += 256) {
        int p = idx & 127, oc = idx >> 7;
        const float* lwr = (const float*)(smem + S_BHI) + p * LWST;
        float o = 0.f;
#pragma unroll
        for (int c = 0; c < 3; ++c)
#pragma unroll
            for (int ki = 0; ki < 3; ++ki) {
                const float* xr = xp + (c*3 + ki) * 132 + p;
#pragma unroll
                for (int kj = 0; kj < 3; ++kj)
                    o += xr[kj] * lwr[(c*9 + ki*3 + kj) * 3 + oc];
            }
        outp[(long)(bimg*3 + oc) * HWp + n0 + p] = o;
    }
}

// ---------------- 3x3 stride-2 pad-1 conv, 3 -> 64 channels -----------------
__global__ __launch_bounds__(256) void k_conv3x3s2(const float* __restrict__ in,
    const float* __restrict__ wt, const float* __restrict__ bias,
    float* __restrict__ outp, int S)
{
    __shared__ float w_s[1728];
    __shared__ float in_s[3][33][33];
    int tid = threadIdx.x;
    for (int i = tid; i < 1728; i += 256) w_s[i] = wt[i];
    int OS = S >> 1;
    int ox0 = blockIdx.x * 16, oy0 = blockIdx.y * 16, b = blockIdx.z;
    for (int idx = tid; idx < 3*33*33; idx += 256) {
        int c = idx / 1089, rem = idx % 1089, r = rem / 33, col = rem % 33;
        int iy = oy0*2 - 1 + r, ix = ox0*2 - 1 + col;
        float v = 0.f;
        if (iy >= 0 && iy < S && ix >= 0 && ix < S)
            v = in[((long)(b*3 + c) * S + iy) * S + ix];
        in_s[c][r][col] = v;
    }
    __syncthreads();
    int ox = tid & 15, oy = tid >> 4;
    float pix[27];
#pragma unroll
    for (int c = 0; c < 3; ++c)
#pragma unroll
        for (int ki = 0; ki < 3; ++ki)
#pragma unroll
            for (int kj = 0; kj < 3; ++kj)
                pix[c*9 + ki*3 + kj] = in_s[c][2*oy + ki][2*ox + kj];
#pragma unroll 4
    for (int oc = 0; oc < 64; ++oc) {
        float acc = bias[oc];
#pragma unroll
        for (int q = 0; q < 27; ++q) acc += pix[q] * w_s[oc*27 + q];
        outp[(((long)b*64 + oc) * OS + oy0 + oy) * OS + ox0 + ox] = acc;
    }
}

// ---------------- 1x1 mod conv ----------------------------------------------
__global__ void k_mod(const float* __restrict__ dx, const float* __restrict__ o256,
                      const float* __restrict__ mw, const float* __restrict__ mb,
                      float* __restrict__ outp)
{
    int t = blockIdx.x * 256 + threadIdx.x;
    if (t >= BB * DH * DH) return;
    int b = t >> 16, p = t & 65535;
    float in6[6];
#pragma unroll
    for (int c = 0; c < 3; ++c) in6[c]     = dx[(b*3 + c)*65536 + p];
#pragma unroll
    for (int c = 0; c < 3; ++c) in6[3 + c] = o256[(b*3 + c)*65536 + p];
#pragma unroll
    for (int oc = 0; oc < 3; ++oc) {
        float a = mb[oc];
#pragma unroll
        for (int ic = 0; ic < 6; ++ic) a += in6[ic] * mw[oc*6 + ic];
        outp[(b*3 + oc)*65536 + p] = a;
    }
}

// ---------------- launch -----------------------------------------------------
extern "C" void kernel_launch(void* const* d_in, const int* in_sizes, int n_in,
                              void* d_out, int out_size)
{
    const float* x      = (const float*)d_in[0];
    const float* W_in   = (const float*)d_in[1];
    const float* W_h1   = (const float*)d_in[2];
    const float* W_h2   = (const float*)d_in[3];
    const float* W_h3   = (const float*)d_in[4];
    const float* W_h4   = (const float*)d_in[5];
    const float* W_out  = (const float*)d_in[6];
    const float* feat_w = (const float*)d_in[7];
    const float* feat_b = (const float*)d_in[8];
    const float* mod_w  = (const float*)d_in[9];
    const float* mod_b  = (const float*)d_in[10];

    float* outF = (float*)d_out;
    float* dout_mod = outF;                       // 2*3*256*256   = 393216
    float* dout_hr  = outF + 393216;              // 2*64*256*256  = 8388608
    float* dout_new = outF + 8781824;             // 8388608
    float* dout_ori = outF + 17170432;            // 8388608
    float* dout_out = outF + 25559040;            // 393216

    float *downx, *outfull, *out256, *ftmp;
    cudaGetSymbolAddress((void**)&downx,   g_down_x);
    cudaGetSymbolAddress((void**)&outfull, g_out_full);
    cudaGetSymbolAddress((void**)&out256,  g_out256);
    cudaGetSymbolAddress((void**)&ftmp,    g_feat_tmp);

    static int smem_set = 0;
    if (!smem_set) {
        cudaFuncSetAttribute(fused_mlp_mma, cudaFuncAttributeMaxDynamicSharedMemorySize,
                             S_TOT);
        smem_set = 1;
    }

    // 1. down_x = bicubic_down2(x)
    k_down2<<<(BB*3*DH*DH + 255)/256, 256>>>(x, downx, nullptr, BB*3, HH);
    // 2. weight split/prep into bf16 hi/lo [k][n]
    k_prep_w<<<320, 256>>>(W_h1, W_h2, W_h3, W_h4, W_out);
    // 3. fused tensor-core MLP + dynamic-filter apply -> out_full
    fused_mlp_mma<<<MROWS/128, 256, S_TOT>>>(x, W_in, outfull);
    // 4. out = down2(out_full); keep copy for mod conv
    k_down2<<<(BB*3*DH*DH + 255)/256, 256>>>(outfull, out256, dout_out, BB*3, HH);
    // 5. down_x_mod = 1x1 conv(concat(down_x, out))
    k_mod<<<(BB*DH*DH + 255)/256, 256>>>(downx, out256, mod_w, mod_b, dout_mod);
    // 6. hr_feature = conv3x3s2(x)
    {
        dim3 g(16, 16, BB);
        k_conv3x3s2<<<g, 256>>>(x, feat_w, feat_b, dout_hr, 512);
    }
    // 7. ori_lr_feature = up2(conv3x3s2(down_x))
    {
        dim3 g(8, 8, BB);
        k_conv3x3s2<<<g, 256>>>(downx, feat_w, feat_b, ftmp, 256);
    }
    k_up2<<<(BB*64*256*256 + 255)/256, 256>>>(ftmp, dout_ori, BB*64, 128);
    // 8. new_lr_feature = up2(conv3x3s2(down_x_mod))
    {
        dim3 g(8, 8, BB);
        k_conv3x3s2<<<g, 256>>>(dout_mod, feat_w, feat_b, ftmp, 256);
    }
    k_up2<<<(BB*64*256*256 + 255)/256, 256>>>(ftmp, dout_new, BB*64, 128);
}